// round 15
// baseline (speedup 1.0000x reference)
#include <cuda_runtime.h>
#include <cuda_bf16.h>
#include <cstdint>
#include <cstddef>

#define NT    4096      // H*W tokens
#define CH    256       // hidden channels
#define CIN   512       // input channels
#define BATCH 4
#define SROW  36        // smem row stride (words), ≡4 mod 32 -> conflict-free fragments
#define NPART (NT / 128)   // 32 score col-tiles per row

// ---------------- scratch (device globals; no allocation in kernel_launch) --------
__device__ float d_fT [(size_t)BATCH * NT * CH];   // fT [b][n][d]
__device__ float d_gT [(size_t)BATCH * NT * CH];   // gT [b][m][d]
__device__ float d_h  [(size_t)BATCH * CH * NT];   // h  [b][d][m]
__device__ float d_fcs[(size_t)BATCH * NT * CH];   // Fcs[b][n][d]
__device__ float d_S  [(size_t)BATCH * NT * NT];   // scores [b][n][m]
__device__ float d_soff[(size_t)BATCH * NT];       // per-row max + ln(sum)
__device__ float d_pmax[(size_t)BATCH * NT * NPART];
__device__ float d_psum[(size_t)BATCH * NT * NPART];
__device__ float d_mean[2 * BATCH * CIN];
__device__ float d_inv [2 * BATCH * CIN];

__device__ __forceinline__ float relu6f(float x) { return fminf(fmaxf(x, 0.0f), 6.0f); }
__device__ __forceinline__ float tf32rna(float x) {
    float r; asm("cvt.rna.tf32.f32 %0, %1;" : "=f"(r) : "f"(x)); return r;
}
// m16n8k8 tf32 MMA (baseline PTX, sm_80+)
__device__ __forceinline__ void mma8(float* d, const uint32_t* a, const uint32_t* b) {
    asm volatile("mma.sync.aligned.m16n8k8.row.col.f32.tf32.tf32.f32 "
                 "{%0,%1,%2,%3},{%4,%5,%6,%7},{%8,%9},{%0,%1,%2,%3};"
                 : "+f"(d[0]), "+f"(d[1]), "+f"(d[2]), "+f"(d[3])
                 : "r"(a[0]), "r"(a[1]), "r"(a[2]), "r"(a[3]), "r"(b[0]), "r"(b[1]));
}
// m16n8k16 bf16 MMA (baseline PTX, sm_80+) — 2x MAC rate of tf32 m16n8k8
__device__ __forceinline__ void mma16(float* d, const uint32_t* a, const uint32_t* b) {
    asm volatile("mma.sync.aligned.m16n8k16.row.col.f32.bf16.bf16.f32 "
                 "{%0,%1,%2,%3},{%4,%5,%6,%7},{%8,%9},{%0,%1,%2,%3};"
                 : "+f"(d[0]), "+f"(d[1]), "+f"(d[2]), "+f"(d[3])
                 : "r"(a[0]), "r"(a[1]), "r"(a[2]), "r"(a[3]), "r"(b[0]), "r"(b[1]));
}

// Store 4 consecutive k floats of one tile row into smem.
// MODE 0: tf32-rounded floats at word col c4. MODE 1: bf16 hi/lo pairs (hi @c4/2, lo @+16).
template<int MODE>
__device__ __forceinline__ void tile_store(float* S, int r, int c4, float4 v) {
    if (MODE == 0) {
        v.x = tf32rna(v.x); v.y = tf32rna(v.y);
        v.z = tf32rna(v.z); v.w = tf32rna(v.w);
        *(float4*)(S + r * SROW + c4) = v;
    } else {
        __nv_bfloat162 h0 = __floats2bfloat162_rn(v.x, v.y);
        __nv_bfloat162 h1 = __floats2bfloat162_rn(v.z, v.w);
        float2 f0 = __bfloat1622float2(h0);
        float2 f1 = __bfloat1622float2(h1);
        __nv_bfloat162 l0 = __floats2bfloat162_rn(v.x - f0.x, v.y - f0.y);
        __nv_bfloat162 l1 = __floats2bfloat162_rn(v.z - f1.x, v.w - f1.y);
        uint32_t* W = (uint32_t*)(S + r * SROW) + (c4 >> 1);
        *(uint2*)(W)      = make_uint2(*(uint32_t*)&h0, *(uint32_t*)&h1);
        *(uint2*)(W + 16) = make_uint2(*(uint32_t*)&l0, *(uint32_t*)&l1);
    }
}

// ---------------- per-(b,c) instance-norm stats, ddof=1 ----------------
__global__ __launch_bounds__(256) void stats_kernel(const float* __restrict__ Fc,
                                                    const float* __restrict__ Fs) {
    int inst  = blockIdx.x;
    int which = blockIdx.y;
    const float* src = (which ? Fs : Fc) + (size_t)inst * NT;
    int tid = threadIdx.x;
    float s = 0.f, ss = 0.f;
    for (int e = tid; e < NT / 4; e += 256) {
        float4 v = ((const float4*)src)[e];
        s  += v.x + v.y + v.z + v.w;
        ss += v.x * v.x + v.y * v.y + v.z * v.z + v.w * v.w;
    }
    for (int o = 16; o; o >>= 1) {
        s  += __shfl_xor_sync(0xffffffffu, s, o);
        ss += __shfl_xor_sync(0xffffffffu, ss, o);
    }
    __shared__ float sb[8], ssb[8];
    if ((tid & 31) == 0) { sb[tid >> 5] = s; ssb[tid >> 5] = ss; }
    __syncthreads();
    if (tid == 0) {
        s = 0.f; ss = 0.f;
        for (int w = 0; w < 8; w++) { s += sb[w]; ss += ssb[w]; }
        float mean = s / (float)NT;
        float var  = (ss - s * mean) / (float)(NT - 1);
        d_mean[which * BATCH * CIN + inst] = mean;
        d_inv [which * BATCH * CIN + inst] = rsqrtf(var + 1e-5f);
    }
}

// ---------------- MMA GEMM: C[M,N] = A[M,K] * B[N,K]^T ---------------------------
// CTA tile (WM*32) x (WN*64), K-chunk 32, WM*WN warps (32x64 warp tile), dbl-buffer.
// MODE 0: single tf32. MODE 1: 2-way split bf16.
// EXPA: A -> exp(a - aoff[row]) at smem-store time (MODE0 only).
// STATS: epilogue emits per-row (max, sum exp) partials over this CTA's N cols.
template<int MODE, int ACT, int EXPA, int WM, int WN, int STATS>
__global__ __launch_bounds__(32 * WM * WN, 1)
void mma_gemm(const float* __restrict__ Ag, const float* __restrict__ Bg,
              const float* __restrict__ bias, const float* __restrict__ aoffg,
              float* __restrict__ Cg, float* __restrict__ pmaxg, float* __restrict__ psumg,
              int K, int lda, int ldb, int ldc,
              size_t bA, size_t bB, size_t bC)
{
    constexpr int M = WM * 32, N = WN * 64;
    constexpr int ABUF = M * SROW, BBUF = N * SROW;
    extern __shared__ float smf[];
    float* SAbase = smf;                 // 2 x ABUF
    float* SBbase = smf + 2 * ABUF;      // 2 x BBUF

    const int tid  = threadIdx.x;
    const int wid  = tid >> 5, lane = tid & 31;
    const int wm   = wid % WM,  wn  = wid / WM;
    const int lr   = lane >> 2, lc  = lane & 3;
    const int rbase = tid >> 3;
    const int c4    = (tid & 7) * 4;

    const float* A = Ag + blockIdx.z * bA + (size_t)(blockIdx.y * M) * lda;
    const float* B = Bg + blockIdx.z * bB + (size_t)(blockIdx.x * N) * ldb;
    float*       C = Cg + blockIdx.z * bC + (size_t)(blockIdx.y * M) * ldc + blockIdx.x * N;

    float acc[2][8][4];
#pragma unroll
    for (int mi = 0; mi < 2; mi++)
#pragma unroll
        for (int nj = 0; nj < 8; nj++)
#pragma unroll
            for (int q = 0; q < 4; q++) acc[mi][nj][q] = 0.f;

    float po[M / 32];
    if (EXPA) {
        const float* Ao = aoffg + blockIdx.z * NT + blockIdx.y * M;
#pragma unroll
        for (int i = 0; i < M / 32; i++) po[i] = Ao[rbase + 32 * i];
    }

    float4 pa[M / 32], pb[N / 32];
#pragma unroll
    for (int i = 0; i < M / 32; i++)
        pa[i] = *(const float4*)(A + (size_t)(rbase + 32 * i) * lda + c4);
#pragma unroll
    for (int i = 0; i < N / 32; i++)
        pb[i] = *(const float4*)(B + (size_t)(rbase + 32 * i) * ldb + c4);

    const int NCH = K / 32;

    // store chunk 0 into buffer 0
    {
#pragma unroll
        for (int i = 0; i < M / 32; i++) {
            float4 va = pa[i];
            if (EXPA) {
                va.x = __expf(va.x - po[i]); va.y = __expf(va.y - po[i]);
                va.z = __expf(va.z - po[i]); va.w = __expf(va.w - po[i]);
            }
            tile_store<MODE>(SAbase, rbase + 32 * i, c4, va);
        }
#pragma unroll
        for (int i = 0; i < N / 32; i++)
            tile_store<MODE>(SBbase, rbase + 32 * i, c4, pb[i]);
    }
    __syncthreads();

    for (int c = 0; c < NCH; c++) {
        const int cur = c & 1;
        const bool more = (c + 1 < NCH);
        if (more) {
#pragma unroll
            for (int i = 0; i < M / 32; i++)
                pa[i] = *(const float4*)(A + (size_t)(rbase + 32 * i) * lda + (c + 1) * 32 + c4);
#pragma unroll
            for (int i = 0; i < N / 32; i++)
                pb[i] = *(const float4*)(B + (size_t)(rbase + 32 * i) * ldb + (c + 1) * 32 + c4);
        }
        const uint32_t* UA = (const uint32_t*)(SAbase + cur * ABUF);
        const uint32_t* UB = (const uint32_t*)(SBbase + cur * BBUF);
        if (MODE == 0) {
#pragma unroll
            for (int ks = 0; ks < 4; ks++) {
                const int k0 = ks * 8;
                uint32_t ah[2][4], bh[8][2];
#pragma unroll
                for (int mi = 0; mi < 2; mi++) {
                    int base = (wm * 32 + mi * 16 + lr) * SROW + k0 + lc;
                    ah[mi][0] = UA[base];            ah[mi][1] = UA[base + 8 * SROW];
                    ah[mi][2] = UA[base + 4];        ah[mi][3] = UA[base + 8 * SROW + 4];
                }
#pragma unroll
                for (int nj = 0; nj < 8; nj++) {
                    int base = (wn * 64 + nj * 8 + lr) * SROW + k0 + lc;
                    bh[nj][0] = UB[base];            bh[nj][1] = UB[base + 4];
                }
#pragma unroll
                for (int mi = 0; mi < 2; mi++)
#pragma unroll
                    for (int nj = 0; nj < 8; nj++)
                        mma8(acc[mi][nj], ah[mi], bh[nj]);
            }
        } else {
#pragma unroll
            for (int s = 0; s < 2; s++) {
                const int k0 = s * 8;
                uint32_t ah[2][4], al[2][4], bh[8][2], bl[8][2];
#pragma unroll
                for (int mi = 0; mi < 2; mi++) {
                    int base = (wm * 32 + mi * 16 + lr) * SROW + k0 + lc;
                    ah[mi][0] = UA[base];            ah[mi][1] = UA[base + 8 * SROW];
                    ah[mi][2] = UA[base + 4];        ah[mi][3] = UA[base + 8 * SROW + 4];
                    al[mi][0] = UA[base + 16];       al[mi][1] = UA[base + 8 * SROW + 16];
                    al[mi][2] = UA[base + 20];       al[mi][3] = UA[base + 8 * SROW + 20];
                }
#pragma unroll
                for (int nj = 0; nj < 8; nj++) {
                    int base = (wn * 64 + nj * 8 + lr) * SROW + k0 + lc;
                    bh[nj][0] = UB[base];            bh[nj][1] = UB[base + 4];
                    bl[nj][0] = UB[base + 16];       bl[nj][1] = UB[base + 20];
                }
#pragma unroll
                for (int mi = 0; mi < 2; mi++)
#pragma unroll
                    for (int nj = 0; nj < 8; nj++) {
                        mma16(acc[mi][nj], ah[mi], bh[nj]);
                        mma16(acc[mi][nj], ah[mi], bl[nj]);
                        mma16(acc[mi][nj], al[mi], bh[nj]);
                    }
            }
        }
        if (more) {
            float* SA = SAbase + (cur ^ 1) * ABUF;
            float* SB = SBbase + (cur ^ 1) * BBUF;
#pragma unroll
            for (int i = 0; i < M / 32; i++) {
                float4 va = pa[i];
                if (EXPA) {
                    va.x = __expf(va.x - po[i]); va.y = __expf(va.y - po[i]);
                    va.z = __expf(va.z - po[i]); va.w = __expf(va.w - po[i]);
                }
                tile_store<MODE>(SA, rbase + 32 * i, c4, va);
            }
#pragma unroll
            for (int i = 0; i < N / 32; i++)
                tile_store<MODE>(SB, rbase + 32 * i, c4, pb[i]);
        }
        __syncthreads();
    }

    // ---- C write ----
#pragma unroll
    for (int mi = 0; mi < 2; mi++) {
        int r = wm * 32 + mi * 16 + lr;
        float b0 = 0.f, b1 = 0.f;
        if (ACT) {
            b0 = bias[blockIdx.y * M + r];
            b1 = bias[blockIdx.y * M + r + 8];
        }
#pragma unroll
        for (int nj = 0; nj < 8; nj++) {
            int col = wn * 64 + nj * 8 + lc * 2;
            float2 v0 = make_float2(acc[mi][nj][0], acc[mi][nj][1]);
            float2 v1 = make_float2(acc[mi][nj][2], acc[mi][nj][3]);
            if (ACT) {
                v0.x = relu6f(v0.x + b0); v0.y = relu6f(v0.y + b0);
                v1.x = relu6f(v1.x + b1); v1.y = relu6f(v1.y + b1);
            }
            *(float2*)(C + (size_t)r * ldc + col)       = v0;
            *(float2*)(C + (size_t)(r + 8) * ldc + col) = v1;
        }
    }

    // ---- fused softmax partial stats (per-row max & sum exp over this CTA's cols) ----
    if (STATS) {
        float* redm = smf;           // [WN * M]
        float* reds = smf + WN * M;  // [WN * M]
        float rmax[2][2], rsum[2][2];
#pragma unroll
        for (int mi = 0; mi < 2; mi++)
#pragma unroll
            for (int hf = 0; hf < 2; hf++) {
                float v = -1e30f;
#pragma unroll
                for (int nj = 0; nj < 8; nj++)
                    v = fmaxf(v, fmaxf(acc[mi][nj][2 * hf], acc[mi][nj][2 * hf + 1]));
                v = fmaxf(v, __shfl_xor_sync(0xffffffffu, v, 1));
                v = fmaxf(v, __shfl_xor_sync(0xffffffffu, v, 2));
                rmax[mi][hf] = v;
            }
        if (lc == 0) {
#pragma unroll
            for (int mi = 0; mi < 2; mi++)
#pragma unroll
                for (int hf = 0; hf < 2; hf++)
                    redm[wn * M + wm * 32 + mi * 16 + hf * 8 + lr] = rmax[mi][hf];
        }
        __syncthreads();
#pragma unroll
        for (int mi = 0; mi < 2; mi++)
#pragma unroll
            for (int hf = 0; hf < 2; hf++) {
                int row = wm * 32 + mi * 16 + hf * 8 + lr;
                float m = redm[row];
#pragma unroll
                for (int w = 1; w < WN; w++) m = fmaxf(m, redm[w * M + row]);
                rmax[mi][hf] = m;
                float s = 0.f;
#pragma unroll
                for (int nj = 0; nj < 8; nj++)
                    s += __expf(acc[mi][nj][2 * hf] - m) + __expf(acc[mi][nj][2 * hf + 1] - m);
                s += __shfl_xor_sync(0xffffffffu, s, 1);
                s += __shfl_xor_sync(0xffffffffu, s, 2);
                rsum[mi][hf] = s;
            }
        if (lc == 0) {
#pragma unroll
            for (int mi = 0; mi < 2; mi++)
#pragma unroll
                for (int hf = 0; hf < 2; hf++)
                    reds[wn * M + wm * 32 + mi * 16 + hf * 8 + lr] = rsum[mi][hf];
        }
        __syncthreads();
        if (wn == 0 && lc == 0) {
#pragma unroll
            for (int mi = 0; mi < 2; mi++)
#pragma unroll
                for (int hf = 0; hf < 2; hf++) {
                    int row = wm * 32 + mi * 16 + hf * 8 + lr;
                    float s = reds[row];
#pragma unroll
                    for (int w = 1; w < WN; w++) s += reds[w * M + row];
                    size_t idx = ((size_t)blockIdx.z * NT + blockIdx.y * M + row) * NPART
                               + blockIdx.x;
                    pmaxg[idx] = rmax[mi][hf];
                    psumg[idx] = s;
                }
        }
    }
}

// ---------------- merge partials: off[row] = gmax + ln(sum_i psum_i * exp(pmax_i-gmax))
__global__ __launch_bounds__(256) void merge_stats(const float* __restrict__ pmax,
                                                   const float* __restrict__ psum,
                                                   float* __restrict__ off) {
    int row  = blockIdx.x * 8 + (threadIdx.x >> 5);
    int lane = threadIdx.x & 31;
    float m = pmax[(size_t)row * NPART + lane];
    float mall = m;
#pragma unroll
    for (int o = 16; o; o >>= 1) mall = fmaxf(mall, __shfl_xor_sync(0xffffffffu, mall, o));
    float s = psum[(size_t)row * NPART + lane] * __expf(m - mall);
#pragma unroll
    for (int o = 16; o; o >>= 1) s += __shfl_xor_sync(0xffffffffu, s, o);
    if (lane == 0) off[row] = mall + logf(s);
}

// ---------------- tensor-core 1x1 conv: C = relu6(W @ X + bias) -------------------
template<int MODE, int TRANSOUT>
__global__ __launch_bounds__(256, 1)
void conv_mma(const float* __restrict__ Wg, const float* __restrict__ Xg,
              const float* __restrict__ bias,
              const float* __restrict__ mean, const float* __restrict__ inv,
              float* __restrict__ Cg, int K, int ldc, size_t bC)
{
    constexpr int ABUF = 128 * SROW;
    constexpr int XBUF = 32 * 132;
    extern __shared__ float smf[];
    float* SAbase = smf;
    float* XSbase = smf + 2 * ABUF;
    float* stage  = smf;

    const int tid  = threadIdx.x;
    const int wid  = tid >> 5, lane = tid & 31;
    const int wm   = wid & 3,  wn2  = wid >> 2;
    const int lr   = lane >> 2, lc  = lane & 3;
    const int rbase = tid >> 3;
    const int c4    = (tid & 7) * 4;
    const int kk    = tid >> 5;
    const int n4    = (tid & 31) * 4;

    const int b  = blockIdx.z;
    const int n0 = blockIdx.x * 128;
    const int r0 = blockIdx.y * 128;
    const float* X = Xg + (size_t)b * K * NT;
    const float* mu = mean ? mean + b * K : nullptr;
    const float* iv = inv  ? inv  + b * K : nullptr;
    float* C = Cg + b * bC;

    float acc[2][8][4];
#pragma unroll
    for (int mi = 0; mi < 2; mi++)
#pragma unroll
        for (int nj = 0; nj < 8; nj++)
#pragma unroll
            for (int q = 0; q < 4; q++) acc[mi][nj][q] = 0.f;

    float4 pa[4], px[4];
    float pm[4], pv[4];

    auto prefetch = [&](int c) {
#pragma unroll
        for (int i = 0; i < 4; i++)
            pa[i] = *(const float4*)(Wg + (size_t)(r0 + rbase + 32 * i) * K + c * 32 + c4);
        if (MODE == 0) {
#pragma unroll
            for (int i = 0; i < 4; i++) {
                int k = c * 32 + kk + 8 * i;
                px[i] = *(const float4*)(X + (size_t)k * NT + n0 + n4);
                pm[i] = mu ? mu[k] : 0.f;
                pv[i] = iv ? iv[k] : 1.f;
            }
        } else {
#pragma unroll
            for (int i = 0; i < 2; i++) {
                int kg = c * 32 + 2 * (kk + 8 * i);
                px[2 * i]     = *(const float4*)(X + (size_t)kg * NT + n0 + n4);
                px[2 * i + 1] = *(const float4*)(X + (size_t)(kg + 1) * NT + n0 + n4);
                pm[2 * i]     = mu ? mu[kg] : 0.f;
                pv[2 * i]     = iv ? iv[kg] : 1.f;
                pm[2 * i + 1] = mu ? mu[kg + 1] : 0.f;
                pv[2 * i + 1] = iv ? iv[kg + 1] : 1.f;
            }
        }
    };

    auto store_buf = [&](int buf) {
        float* SA  = SAbase + buf * ABUF;
        float* XS0 = XSbase + buf * XBUF;
#pragma unroll
        for (int i = 0; i < 4; i++)
            tile_store<MODE>(SA, rbase + 32 * i, c4, pa[i]);
        if (MODE == 0) {
#pragma unroll
            for (int i = 0; i < 4; i++) {
                int k = kk + 8 * i;
                float4 v = px[i];
                v.x = (v.x - pm[i]) * pv[i]; v.y = (v.y - pm[i]) * pv[i];
                v.z = (v.z - pm[i]) * pv[i]; v.w = (v.w - pm[i]) * pv[i];
                v.x = tf32rna(v.x); v.y = tf32rna(v.y);
                v.z = tf32rna(v.z); v.w = tf32rna(v.w);
                *(float4*)(XS0 + k * 132 + n4) = v;
            }
        } else {
            float* XS1 = XS0 + 16 * 132;
#pragma unroll
            for (int i = 0; i < 2; i++) {
                int kp = kk + 8 * i;
                float4 xe = px[2 * i], xo = px[2 * i + 1];
                xe.x = (xe.x - pm[2*i]) * pv[2*i]; xe.y = (xe.y - pm[2*i]) * pv[2*i];
                xe.z = (xe.z - pm[2*i]) * pv[2*i]; xe.w = (xe.w - pm[2*i]) * pv[2*i];
                xo.x = (xo.x - pm[2*i+1]) * pv[2*i+1]; xo.y = (xo.y - pm[2*i+1]) * pv[2*i+1];
                xo.z = (xo.z - pm[2*i+1]) * pv[2*i+1]; xo.w = (xo.w - pm[2*i+1]) * pv[2*i+1];
                float e[4] = {xe.x, xe.y, xe.z, xe.w};
                float o[4] = {xo.x, xo.y, xo.z, xo.w};
                uint32_t hw[4], lw[4];
#pragma unroll
                for (int j = 0; j < 4; j++) {
                    __nv_bfloat162 h = __floats2bfloat162_rn(e[j], o[j]);
                    float2 hf = __bfloat1622float2(h);
                    __nv_bfloat162 l = __floats2bfloat162_rn(e[j] - hf.x, o[j] - hf.y);
                    hw[j] = *(uint32_t*)&h;
                    lw[j] = *(uint32_t*)&l;
                }
                *(uint4*)((uint32_t*)XS0 + kp * 132 + n4) = make_uint4(hw[0], hw[1], hw[2], hw[3]);
                *(uint4*)((uint32_t*)XS1 + kp * 132 + n4) = make_uint4(lw[0], lw[1], lw[2], lw[3]);
            }
        }
    };

    const int NCH = K / 32;
    prefetch(0);
    store_buf(0);
    __syncthreads();

    for (int c = 0; c < NCH; c++) {
        const int cur = c & 1;
        const bool more = (c + 1 < NCH);
        if (more) prefetch(c + 1);

        const uint32_t* UA  = (const uint32_t*)(SAbase + cur * ABUF);
        const uint32_t* UX0 = (const uint32_t*)(XSbase + cur * XBUF);
        if (MODE == 0) {
#pragma unroll
            for (int ks = 0; ks < 4; ks++) {
                const int k0 = ks * 8;
                uint32_t ah[2][4], bh[8][2];
#pragma unroll
                for (int mi = 0; mi < 2; mi++) {
                    int base = (wm * 32 + mi * 16 + lr) * SROW + k0 + lc;
                    ah[mi][0] = UA[base];            ah[mi][1] = UA[base + 8 * SROW];
                    ah[mi][2] = UA[base + 4];        ah[mi][3] = UA[base + 8 * SROW + 4];
                }
#pragma unroll
                for (int nj = 0; nj < 8; nj++) {
                    int col = wn2 * 64 + nj * 8 + lr;
                    bh[nj][0] = UX0[(k0 + lc) * 132 + col];
                    bh[nj][1] = UX0[(k0 + lc + 4) * 132 + col];
                }
#pragma unroll
                for (int mi = 0; mi < 2; mi++)
#pragma unroll
                    for (int nj = 0; nj < 8; nj++)
                        mma8(acc[mi][nj], ah[mi], bh[nj]);
            }
        } else {
            const uint32_t* UX1 = UX0 + 16 * 132;
#pragma unroll
            for (int s = 0; s < 2; s++) {
                const int k0 = s * 8;
                uint32_t ah[2][4], al[2][4], bh[8][2], bl[8][2];
#pragma unroll
                for (int mi = 0; mi < 2; mi++) {
                    int base = (wm * 32 + mi * 16 + lr) * SROW + k0 + lc;
                    ah[mi][0] = UA[base];            ah[mi][1] = UA[base + 8 * SROW];
                    ah[mi][2] = UA[base + 4];        ah[mi][3] = UA[base + 8 * SROW + 4];
                    al[mi][0] = UA[base + 16];       al[mi][1] = UA[base + 8 * SROW + 16];
                    al[mi][2] = UA[base + 20];       al[mi][3] = UA[base + 8 * SROW + 20];
                }
#pragma unroll
                for (int nj = 0; nj < 8; nj++) {
                    int col = wn2 * 64 + nj * 8 + lr;
                    bh[nj][0] = UX0[(k0 + lc) * 132 + col];
                    bh[nj][1] = UX0[(k0 + lc + 4) * 132 + col];
                    bl[nj][0] = UX1[(k0 + lc) * 132 + col];
                    bl[nj][1] = UX1[(k0 + lc + 4) * 132 + col];
                }
#pragma unroll
                for (int mi = 0; mi < 2; mi++)
#pragma unroll
                    for (int nj = 0; nj < 8; nj++) {
                        mma16(acc[mi][nj], ah[mi], bh[nj]);
                        mma16(acc[mi][nj], ah[mi], bl[nj]);
                        mma16(acc[mi][nj], al[mi], bh[nj]);
                    }
            }
        }
        if (more) store_buf(cur ^ 1);
        __syncthreads();
    }

    if (!TRANSOUT) {
#pragma unroll
        for (int mi = 0; mi < 2; mi++) {
            int r = wm * 32 + mi * 16 + lr;
            float b0 = bias[r0 + r], b1 = bias[r0 + r + 8];
#pragma unroll
            for (int nj = 0; nj < 8; nj++) {
                int col = wn2 * 64 + nj * 8 + lc * 2;
                float2 v0 = make_float2(relu6f(acc[mi][nj][0] + b0),
                                        relu6f(acc[mi][nj][1] + b0));
                float2 v1 = make_float2(relu6f(acc[mi][nj][2] + b1),
                                        relu6f(acc[mi][nj][3] + b1));
                *(float2*)(C + (size_t)(r0 + r) * ldc + n0 + col)     = v0;
                *(float2*)(C + (size_t)(r0 + r + 8) * ldc + n0 + col) = v1;
            }
        }
    } else {
#pragma unroll
        for (int mi = 0; mi < 2; mi++) {
            int r = wm * 32 + mi * 16 + lr;
            float b0 = bias[r0 + r], b1 = bias[r0 + r + 8];
#pragma unroll
            for (int nj = 0; nj < 8; nj++) {
                int nl = wn2 * 64 + nj * 8 + lc * 2;
                stage[(size_t)nl * 132 + r]           = relu6f(acc[mi][nj][0] + b0);
                stage[(size_t)(nl + 1) * 132 + r]     = relu6f(acc[mi][nj][1] + b0);
                stage[(size_t)nl * 132 + r + 8]       = relu6f(acc[mi][nj][2] + b1);
                stage[(size_t)(nl + 1) * 132 + r + 8] = relu6f(acc[mi][nj][3] + b1);
            }
        }
        __syncthreads();
#pragma unroll
        for (int i = 0; i < 16; i++) {
            int e = tid + i * 256;
            int n = e >> 5, r4 = (e & 31) * 4;
            *(float4*)(C + (size_t)(n0 + n) * ldc + r0 + r4) = *(const float4*)(stage + n * 132 + r4);
        }
    }
}

// ---------------- launch ----------------
extern "C" void kernel_launch(void* const* d_in, const int* in_sizes, int n_in,
                              void* d_out, int out_size) {
    const float* Fc    = (const float*)d_in[0];
    const float* Fs    = (const float*)d_in[1];
    const float* f_w   = (const float*)d_in[2];
    const float* f_b   = (const float*)d_in[3];
    const float* g_w   = (const float*)d_in[4];
    const float* g_b   = (const float*)d_in[5];
    const float* h_w   = (const float*)d_in[6];
    const float* h_b   = (const float*)d_in[7];
    const float* out_w = (const float*)d_in[8];
    const float* out_b = (const float*)d_in[9];
    float* out = (float*)d_out;

    float *pfT, *pgT, *ph, *pfcs, *pS, *psoff, *ppmax, *ppsum, *pmean, *pinv;
    cudaGetSymbolAddress((void**)&pfT,   d_fT);
    cudaGetSymbolAddress((void**)&pgT,   d_gT);
    cudaGetSymbolAddress((void**)&ph,    d_h);
    cudaGetSymbolAddress((void**)&pfcs,  d_fcs);
    cudaGetSymbolAddress((void**)&pS,    d_S);
    cudaGetSymbolAddress((void**)&psoff, d_soff);
    cudaGetSymbolAddress((void**)&ppmax, d_pmax);
    cudaGetSymbolAddress((void**)&ppsum, d_psum);
    cudaGetSymbolAddress((void**)&pmean, d_mean);
    cudaGetSymbolAddress((void**)&pinv,  d_inv);

    const int SM_G1 = 2 * (128 + 128) * SROW * 4;           // 73728
    const int SM_G2 = 2 * (64 + 256) * SROW * 4;            // 92160
    const int SM_C  = (2 * 128 * SROW + 2 * 32 * 132) * 4;  // 70656
    cudaFuncSetAttribute(mma_gemm<1, 0, 0, 4, 2, 1>, cudaFuncAttributeMaxDynamicSharedMemorySize, SM_G1);
    cudaFuncSetAttribute(mma_gemm<0, 0, 1, 2, 4, 0>, cudaFuncAttributeMaxDynamicSharedMemorySize, SM_G2);
    cudaFuncSetAttribute(mma_gemm<0, 1, 0, 4, 2, 0>, cudaFuncAttributeMaxDynamicSharedMemorySize, SM_G1);
    cudaFuncSetAttribute(conv_mma<1, 1>,             cudaFuncAttributeMaxDynamicSharedMemorySize, SM_C);
    cudaFuncSetAttribute(conv_mma<0, 0>,             cudaFuncAttributeMaxDynamicSharedMemorySize, SM_C);

    stats_kernel<<<dim3(BATCH * CIN, 2), 256>>>(Fc, Fs);

    // fT[n][d] = relu6(f_w @ mvn(Fc) + f_b)^T   (bf16 split)
    conv_mma<1, 1><<<dim3(NT / 128, CH / 128, BATCH), 256, SM_C>>>(
        f_w, Fc, f_b, pmean, pinv, pfT, CIN, CH, (size_t)NT * CH);
    // gT[m][d] = relu6(g_w @ mvn(Fs) + g_b)^T   (bf16 split)
    conv_mma<1, 1><<<dim3(NT / 128, CH / 128, BATCH), 256, SM_C>>>(
        g_w, Fs, g_b, pmean + BATCH * CIN, pinv + BATCH * CIN, pgT, CIN, CH, (size_t)NT * CH);
    // h[d][m] = relu6(h_w @ Fs + h_b)           (1xtf32)
    conv_mma<0, 0><<<dim3(NT / 128, CH / 128, BATCH), 256, SM_C>>>(
        h_w, Fs, h_b, nullptr, nullptr, ph, CIN, NT, (size_t)CH * NT);

    // S[n][m] = fT . gT^T   (bf16 split) + fused per-tile softmax partials
    mma_gemm<1, 0, 0, 4, 2, 1><<<dim3(NT / 128, NT / 128, BATCH), 256, SM_G1>>>(
        pfT, pgT, nullptr, nullptr, pS, ppmax, ppsum, CH, CH, CH, NT,
        (size_t)NT * CH, (size_t)NT * CH, (size_t)NT * NT);

    // merge partials -> off[row] = max + ln(sum exp)
    merge_stats<<<BATCH * NT / 8, 256>>>(ppmax, ppsum, psoff);

    // fcs[n][d] = softmax(S) . h^T   (1xtf32, exp at A-tile store; 64x256 tile, S read once)
    mma_gemm<0, 0, 1, 2, 4, 0><<<dim3(1, NT / 64, BATCH), 256, SM_G2>>>(
        pS, ph, nullptr, psoff, pfcs, nullptr, nullptr, NT, NT, NT, CH,
        (size_t)NT * NT, (size_t)CH * NT, (size_t)NT * CH);

    // out[r][n] = relu6(out_w @ fcs^T + out_b)  (1xtf32)
    mma_gemm<0, 1, 0, 4, 2, 0><<<dim3(NT / 128, CIN / 128, BATCH), 256, SM_G1>>>(
        out_w, pfcs, out_b, nullptr, out, nullptr, nullptr, CH, CH, CH, NT,
        (size_t)0, (size_t)NT * CH, (size_t)CIN * NT);
}